// round 12
// baseline (speedup 1.0000x reference)
#include <cuda_runtime.h>
#include <cuda_fp16.h>
#include <cstdint>

// Problem constants
#define H     2048
#define NTOK  2048      // B*S
#define MR    512       // routed intermediate
#define MSH   1024      // shared intermediate
#define NEXP  8
#define NJOBS 9

// GEMM tiling (fp16 operands, m16n8k16)
#define BM   128
#define GUBN 64         // gateup N tile (per matrix g/u)
#define DBN  128        // down N tile
#define BKH  64         // K halfs per smem tile (4 x k16 steps)
#define S36  36         // smem row stride in uint32 words (32 half2 + 4 pad)
#define NSTG 3

// -------- scratch (no mallocs allowed) --------
__device__ int   d_counts[NEXP];
__device__ int   d_tok[NEXP * NTOK];
__device__ float d_wt [NEXP * NTOK];

__device__ __half g_xh  [(size_t)NTOK * H];
__device__ __half g_wgT [(size_t)NEXP * MR * H];   // [e][n=MR][k=H]
__device__ __half g_wuT [(size_t)NEXP * MR * H];
__device__ __half g_swgT[(size_t)MSH * H];         // [n=MSH][k=H]
__device__ __half g_swuT[(size_t)MSH * H];
__device__ __half g_wdT [(size_t)NEXP * H * MR];   // [e][n=H][k=MR]
__device__ __half g_swdT[(size_t)H * MSH];         // [n=H][k=MSH]
#define HB_SHOFF ((size_t)NEXP * NTOK * MR)
__device__ __half g_hb[HB_SHOFF + (size_t)NTOK * MSH];

// -------- helpers --------
__device__ __forceinline__ void cp16(void* smem_dst, const void* gmem_src) {
    uint32_t s = (uint32_t)__cvta_generic_to_shared(smem_dst);
    asm volatile("cp.async.cg.shared.global [%0], [%1], 16;\n" :: "r"(s), "l"(gmem_src));
}
__device__ __forceinline__ void cp_commit() { asm volatile("cp.async.commit_group;\n"); }
__device__ __forceinline__ void cp_wait0()  { asm volatile("cp.async.wait_group 0;\n"); }
__device__ __forceinline__ void cp_wait1()  { asm volatile("cp.async.wait_group 1;\n"); }

// m16n8k16 fp16 MMA, fp32 accumulate
__device__ __forceinline__ void mma_f16(float* c, const uint32_t* a, const uint32_t* b) {
    asm volatile(
        "mma.sync.aligned.m16n8k16.row.col.f32.f16.f16.f32 "
        "{%0,%1,%2,%3}, {%4,%5,%6,%7}, {%8,%9}, {%0,%1,%2,%3};\n"
        : "+f"(c[0]), "+f"(c[1]), "+f"(c[2]), "+f"(c[3])
        : "r"(a[0]), "r"(a[1]), "r"(a[2]), "r"(a[3]),
          "r"(b[0]), "r"(b[1]));
}

// -------- kernel A1: transpose+convert all weights to fp16 [N][K] --------
// 32x32 tiles; 30720 blocks total, segment decoded from blockIdx.x.
__global__ void transpose_cvt_kernel(
    const float* __restrict__ Wg,  const float* __restrict__ Wu,
    const float* __restrict__ sWg, const float* __restrict__ sWu,
    const float* __restrict__ Wd,  const float* __restrict__ sWd)
{
    __shared__ alignas(16) __half st[32][40];
    int b = blockIdx.x;
    const float* src; __half* dst; int K, N;
    if (b < 8192)       { int e = b >> 10; b &= 1023; src = Wg  + (size_t)e * H * MR; dst = g_wgT + (size_t)e * MR * H; K = H;   N = MR; }
    else if (b < 16384) { b -= 8192;  int e = b >> 10; b &= 1023; src = Wu + (size_t)e * H * MR; dst = g_wuT + (size_t)e * MR * H; K = H; N = MR; }
    else if (b < 18432) { b -= 16384; src = sWg; dst = g_swgT; K = H;   N = MSH; }
    else if (b < 20480) { b -= 18432; src = sWu; dst = g_swuT; K = H;   N = MSH; }
    else if (b < 28672) { b -= 20480; int e = b >> 10; b &= 1023; src = Wd + (size_t)e * MR * H; dst = g_wdT + (size_t)e * H * MR; K = MR; N = H; }
    else                { b -= 28672; src = sWd; dst = g_swdT; K = MSH; N = H; }

    int tN = N / 32;
    int bk = b / tN, bn = b % tN;
    int t = threadIdx.x;
    int kl = t >> 3;          // 0..31
    int nl = (t & 7) * 4;     // 0..28
    float4 v = *(const float4*)(src + (size_t)(bk * 32 + kl) * N + bn * 32 + nl);
    st[nl + 0][kl] = __float2half_rn(v.x);
    st[nl + 1][kl] = __float2half_rn(v.y);
    st[nl + 2][kl] = __float2half_rn(v.z);
    st[nl + 3][kl] = __float2half_rn(v.w);
    __syncthreads();
    int nr = t >> 3;          // out row (n)
    int kc = (t & 7) * 4;     // out k start
    *(uint2*)(dst + (size_t)(bn * 32 + nr) * K + bk * 32 + kc) = *(uint2*)&st[nr][kc];
}

// -------- kernel A2: x -> fp16 straight copy --------
__global__ void cvt_x_kernel(const float4* __restrict__ x) {
    __half2* d = reinterpret_cast<__half2*>(g_xh);
    const size_t total = (size_t)NTOK * H / 4;
    size_t stride = (size_t)gridDim.x * blockDim.x;
    for (size_t i = (size_t)blockIdx.x * blockDim.x + threadIdx.x; i < total; i += stride) {
        float4 v = x[i];
        d[2 * i]     = __floats2half2_rn(v.x, v.y);
        d[2 * i + 1] = __floats2half2_rn(v.z, v.w);
    }
}

// -------- kernel 0: reset routing counts --------
__global__ void reset_kernel() {
    if (threadIdx.x < NEXP) d_counts[threadIdx.x] = 0;
}

// -------- kernel 1: gate logits + top2 + softmax + route lists --------
__global__ void gate_kernel(const float* __restrict__ x, const float* __restrict__ gw) {
    int warp = blockIdx.x * (blockDim.x >> 5) + (threadIdx.x >> 5);
    int lane = threadIdx.x & 31;
    if (warp >= NTOK) return;
    int t = warp;
    const float4* x4 = reinterpret_cast<const float4*>(x + (size_t)t * H);
    const float4* g4 = reinterpret_cast<const float4*>(gw);
    float acc[NEXP];
#pragma unroll
    for (int e = 0; e < NEXP; e++) acc[e] = 0.f;
    for (int i = lane; i < H / 4; i += 32) {
        float4 xv = x4[i];
#pragma unroll
        for (int e = 0; e < NEXP; e++) {
            float4 gv = g4[e * (H / 4) + i];
            acc[e] += xv.x * gv.x + xv.y * gv.y + xv.z * gv.z + xv.w * gv.w;
        }
    }
#pragma unroll
    for (int e = 0; e < NEXP; e++)
#pragma unroll
        for (int o = 16; o; o >>= 1) acc[e] += __shfl_xor_sync(0xffffffffu, acc[e], o);
    if (lane == 0) {
        int i0 = 0; float v0 = acc[0];
#pragma unroll
        for (int e = 1; e < NEXP; e++) if (acc[e] > v0) { v0 = acc[e]; i0 = e; }
        int i1 = -1; float v1 = -1e30f;
#pragma unroll
        for (int e = 0; e < NEXP; e++) if (e != i0 && acc[e] > v1) { v1 = acc[e]; i1 = e; }
        float e1 = __expf(v1 - v0);
        float s  = 1.f + e1;
        float w0 = 1.f / s, w1 = e1 / s;
        int p0 = atomicAdd(&d_counts[i0], 1);
        d_tok[i0 * NTOK + p0] = t; d_wt[i0 * NTOK + p0] = w0;
        int p1 = atomicAdd(&d_counts[i1], 1);
        d_tok[i1 * NTOK + p1] = t; d_wt[i1 * NTOK + p1] = w1;
    }
}

// -------- kernel 2: fp16 gate+up dual-GEMM + SiLU*u epilogue --------
// A = x fp16 (gathered rows, k-contiguous); B = WgT/WuT [n][k] fp16.
__global__ __launch_bounds__(256, 2) void gateup_kernel() {
    const int  job = blockIdx.z;
    const bool sh  = (job == NEXP);
    const int  Mdim = sh ? MSH : MR;
    const int  cnt  = sh ? NTOK : d_counts[job];
    const int  row0 = blockIdx.y * BM;
    const int  col0 = blockIdx.x * GUBN;
    if (row0 >= cnt || col0 >= Mdim) return;

    const __half* BgT = sh ? g_swgT : g_wgT + (size_t)job * MR * H;
    const __half* BuT = sh ? g_swuT : g_wuT + (size_t)job * MR * H;

    extern __shared__ uint32_t smp[];
    uint32_t* As  = smp;                        // [NSTG][BM*S36]
    uint32_t* Bgs = smp + NSTG * BM * S36;      // [NSTG][GUBN*S36]
    uint32_t* Bus = Bgs + NSTG * GUBN * S36;

    const int tid = threadIdx.x;
    const int lane = tid & 31;
    const int wid = tid >> 5;
    const int warp_m = wid & 3;   // 4 warps on M
    const int warp_n = wid >> 2;  // 2 warps on N
    const int g_r = lane >> 2;
    const int g_c = lane & 3;

    // A: BM x BKH halfs = 1024 x 16B chunks -> 4/thread
    uint32_t aoff[4]; int adst[4];
#pragma unroll
    for (int j = 0; j < 4; j++) {
        int idx = tid + j * 256;
        int m = idx >> 3, kc = idx & 7;
        int gl = row0 + m; if (gl >= cnt) gl = cnt - 1;
        int tok = sh ? gl : d_tok[job * NTOK + gl];
        aoff[j] = (uint32_t)(tok * H + kc * 8);
        adst[j] = m * S36 + kc * 4;
    }
    // B: GUBN x BKH halfs = 512 chunks per matrix -> 2/thread
    uint32_t boff[2]; int bdst[2];
#pragma unroll
    for (int j = 0; j < 2; j++) {
        int idx = tid + j * 256;
        int n = idx >> 3, kc = idx & 7;
        boff[j] = (uint32_t)((col0 + n) * H + kc * 8);
        bdst[j] = n * S36 + kc * 4;
    }

    float accg[2][4][4], accu[2][4][4];
#pragma unroll
    for (int a = 0; a < 2; a++)
#pragma unroll
        for (int b = 0; b < 4; b++)
#pragma unroll
            for (int c = 0; c < 4; c++) { accg[a][b][c] = 0.f; accu[a][b][c] = 0.f; }

    const int KT = H / BKH;   // 32

    // prologue: stages 0,1
#pragma unroll
    for (int s = 0; s < 2; s++) {
        uint32_t adv = (uint32_t)s * BKH;
#pragma unroll
        for (int j = 0; j < 4; j++) cp16(As + s * BM * S36 + adst[j], g_xh + aoff[j] + adv);
#pragma unroll
        for (int j = 0; j < 2; j++) {
            cp16(Bgs + s * GUBN * S36 + bdst[j], BgT + boff[j] + adv);
            cp16(Bus + s * GUBN * S36 + bdst[j], BuT + boff[j] + adv);
        }
        cp_commit();
    }

    for (int kt = 0; kt < KT; kt++) {
        if (kt < KT - 1) cp_wait1(); else cp_wait0();
        __syncthreads();

        if (kt + 2 < KT) {
            int nb = (kt + 2) % NSTG;
            uint32_t adv = (uint32_t)(kt + 2) * BKH;
#pragma unroll
            for (int j = 0; j < 4; j++) cp16(As + nb * BM * S36 + adst[j], g_xh + aoff[j] + adv);
#pragma unroll
            for (int j = 0; j < 2; j++) {
                cp16(Bgs + nb * GUBN * S36 + bdst[j], BgT + boff[j] + adv);
                cp16(Bus + nb * GUBN * S36 + bdst[j], BuT + boff[j] + adv);
            }
            cp_commit();
        }

        const int st = kt % NSTG;
        const uint32_t* Ac  = As  + st * BM * S36;
        const uint32_t* Bgc = Bgs + st * GUBN * S36;
        const uint32_t* Buc = Bus + st * GUBN * S36;

#pragma unroll
        for (int ks = 0; ks < BKH / 16; ks++) {   // 4 x k16
            uint32_t af[2][4], bg[4][2], bu[4][2];
#pragma unroll
            for (int mf = 0; mf < 2; mf++) {
                int rb = warp_m * 32 + mf * 16 + g_r;
                af[mf][0] = Ac[rb * S36       + ks * 8 + g_c];
                af[mf][1] = Ac[(rb + 8) * S36 + ks * 8 + g_c];
                af[mf][2] = Ac[rb * S36       + ks * 8 + g_c + 4];
                af[mf][3] = Ac[(rb + 8) * S36 + ks * 8 + g_c + 4];
            }
#pragma unroll
            for (int nf = 0; nf < 4; nf++) {
                int cb = warp_n * 32 + nf * 8 + g_r;
                bg[nf][0] = Bgc[cb * S36 + ks * 8 + g_c];
                bg[nf][1] = Bgc[cb * S36 + ks * 8 + g_c + 4];
                bu[nf][0] = Buc[cb * S36 + ks * 8 + g_c];
                bu[nf][1] = Buc[cb * S36 + ks * 8 + g_c + 4];
            }
#pragma unroll
            for (int mf = 0; mf < 2; mf++)
#pragma unroll
                for (int nf = 0; nf < 4; nf++) {
                    mma_f16(accg[mf][nf], af[mf], bg[nf]);
                    mma_f16(accu[mf][nf], af[mf], bu[nf]);
                }
        }
    }

    // epilogue: silu(g)*u -> fp16 h (half2 stores, cols 2g_c/2g_c+1 adjacent)
    __half* hb = g_hb + (sh ? HB_SHOFF : (size_t)job * NTOK * MR);
#pragma unroll
    for (int mf = 0; mf < 2; mf++)
#pragma unroll
        for (int nf = 0; nf < 4; nf++) {
            int c0 = col0 + warp_n * 32 + nf * 8 + g_c * 2;
#pragma unroll
            for (int half_r = 0; half_r < 2; half_r++) {
                int r = warp_m * 32 + mf * 16 + g_r + half_r * 8;
                int gr = row0 + r;
                if (gr < cnt) {
                    float g0 = accg[mf][nf][half_r * 2 + 0], u0 = accu[mf][nf][half_r * 2 + 0];
                    float g1 = accg[mf][nf][half_r * 2 + 1], u1 = accu[mf][nf][half_r * 2 + 1];
                    float h0 = g0 / (1.f + __expf(-g0)) * u0;
                    float h1 = g1 / (1.f + __expf(-g1)) * u1;
                    *reinterpret_cast<__half2*>(hb + (size_t)gr * Mdim + c0) =
                        __floats2half2_rn(h0, h1);
                }
            }
        }
}

// -------- kernel 3: fp16 down-proj --------
// SHARED=true: dense shared expert (plain stores); false: routed atomics on top.
template <bool SHARED>
__global__ __launch_bounds__(256, 2) void down_kernel(float* __restrict__ y) {
    const int  job  = SHARED ? 0 : blockIdx.z;
    const int  Kdim = SHARED ? MSH : MR;
    const int  cnt  = SHARED ? NTOK : d_counts[job];
    const int  row0 = blockIdx.y * BM;
    const int  col0 = blockIdx.x * DBN;
    if (row0 >= cnt) return;

    const __half* Bp = SHARED ? g_swdT : g_wdT + (size_t)job * H * MR;  // [n=H][k]
    const __half* Ap = SHARED ? g_hb + HB_SHOFF : g_hb + (size_t)job * NTOK * MR;

    extern __shared__ uint32_t smp[];
    uint32_t* As = smp;                     // [NSTG][BM*S36]
    uint32_t* Bs = smp + NSTG * BM * S36;   // [NSTG][DBN*S36]

    const int tid = threadIdx.x;
    const int lane = tid & 31;
    const int wid = tid >> 5;
    const int warp_m = wid & 3;
    const int warp_n = wid >> 2;
    const int g_r = lane >> 2;
    const int g_c = lane & 3;

    // A: BM x BKH halfs -> 4 chunks/thread
    uint32_t aoff[4]; int adst[4];
#pragma unroll
    for (int j = 0; j < 4; j++) {
        int idx = tid + j * 256;
        int m = idx >> 3, kc = idx & 7;
        aoff[j] = (uint32_t)((row0 + m) * Kdim + kc * 8);
        adst[j] = m * S36 + kc * 4;
    }
    // B: DBN x BKH halfs -> 4 chunks/thread
    uint32_t boff[4]; int bdst[4];
#pragma unroll
    for (int j = 0; j < 4; j++) {
        int idx = tid + j * 256;
        int n = idx >> 3, kc = idx & 7;
        boff[j] = (uint32_t)((col0 + n) * Kdim + kc * 8);
        bdst[j] = n * S36 + kc * 4;
    }

    float acc[2][8][4];
#pragma unroll
    for (int a = 0; a < 2; a++)
#pragma unroll
        for (int b = 0; b < 8; b++)
#pragma unroll
            for (int c = 0; c < 4; c++) acc[a][b][c] = 0.f;

    const int KT = Kdim / BKH;   // 8 routed, 16 shared

#pragma unroll
    for (int s = 0; s < 2; s++) {
        uint32_t adv = (uint32_t)s * BKH;
#pragma unroll
        for (int j = 0; j < 4; j++) cp16(As + s * BM * S36 + adst[j], Ap + aoff[j] + adv);
#pragma unroll
        for (int j = 0; j < 4; j++) cp16(Bs + s * DBN * S36 + bdst[j], Bp + boff[j] + adv);
        cp_commit();
    }

    for (int kt = 0; kt < KT; kt++) {
        if (kt < KT - 1) cp_wait1(); else cp_wait0();
        __syncthreads();

        if (kt + 2 < KT) {
            int nb = (kt + 2) % NSTG;
            uint32_t adv = (uint32_t)(kt + 2) * BKH;
#pragma unroll
            for (int j = 0; j < 4; j++) cp16(As + nb * BM * S36 + adst[j], Ap + aoff[j] + adv);
#pragma unroll
            for (int j = 0; j < 4; j++) cp16(Bs + nb * DBN * S36 + bdst[j], Bp + boff[j] + adv);
            cp_commit();
        }

        const int st = kt % NSTG;
        const uint32_t* Ac = As + st * BM * S36;
        const uint32_t* Bc = Bs + st * DBN * S36;

#pragma unroll
        for (int ks = 0; ks < BKH / 16; ks++) {
            uint32_t af[2][4], bf[8][2];
#pragma unroll
            for (int mf = 0; mf < 2; mf++) {
                int rb = warp_m * 32 + mf * 16 + g_r;
                af[mf][0] = Ac[rb * S36       + ks * 8 + g_c];
                af[mf][1] = Ac[(rb + 8) * S36 + ks * 8 + g_c];
                af[mf][2] = Ac[rb * S36       + ks * 8 + g_c + 4];
                af[mf][3] = Ac[(rb + 8) * S36 + ks * 8 + g_c + 4];
            }
#pragma unroll
            for (int nf = 0; nf < 8; nf++) {
                int cb = warp_n * 64 + nf * 8 + g_r;
                bf[nf][0] = Bc[cb * S36 + ks * 8 + g_c];
                bf[nf][1] = Bc[cb * S36 + ks * 8 + g_c + 4];
            }
#pragma unroll
            for (int mf = 0; mf < 2; mf++)
#pragma unroll
                for (int nf = 0; nf < 8; nf++)
                    mma_f16(acc[mf][nf], af[mf], bf[nf]);
        }
    }

    // epilogue
#pragma unroll
    for (int mf = 0; mf < 2; mf++)
#pragma unroll
        for (int nf = 0; nf < 8; nf++)
#pragma unroll
            for (int i = 0; i < 4; i++) {
                int r = warp_m * 32 + mf * 16 + g_r + ((i >= 2) ? 8 : 0);
                int c = warp_n * 64 + nf * 8 + g_c * 2 + (i & 1);
                int gr = row0 + r;
                if (gr < cnt) {
                    if (SHARED) {
                        y[(size_t)gr * H + col0 + c] = acc[mf][nf][i];
                    } else {
                        int   tok = d_tok[job * NTOK + gr];
                        float w   = d_wt[job * NTOK + gr];
                        atomicAdd(&y[(size_t)tok * H + col0 + c], w * acc[mf][nf][i]);
                    }
                }
            }
}

extern "C" void kernel_launch(void* const* d_in, const int* in_sizes, int n_in,
                              void* d_out, int out_size) {
    const float* x   = (const float*)d_in[0];
    const float* gw  = (const float*)d_in[1];
    const float* Wg  = (const float*)d_in[2];
    const float* Wu  = (const float*)d_in[3];
    const float* Wd  = (const float*)d_in[4];
    const float* sWg = (const float*)d_in[5];
    const float* sWu = (const float*)d_in[6];
    const float* sWd = (const float*)d_in[7];
    float* y = (float*)d_out;

    // 1) prep: weight transposes -> fp16 [N][K]; x -> fp16
    transpose_cvt_kernel<<<30720, 256>>>(Wg, Wu, sWg, sWu, Wd, sWd);
    cvt_x_kernel<<<4096, 256>>>((const float4*)x);

    // 2) routing
    reset_kernel<<<1, 32>>>();
    gate_kernel<<<NTOK / 8, 256>>>(x, gw);

    const int smem_gu = NSTG * (BM * S36 + 2 * GUBN * S36) * 4;   // 110592
    const int smem_dn = NSTG * (BM * S36 + DBN * S36) * 4;        // 110592
    cudaFuncSetAttribute(gateup_kernel,      cudaFuncAttributeMaxDynamicSharedMemorySize, smem_gu);
    cudaFuncSetAttribute(down_kernel<true>,  cudaFuncAttributeMaxDynamicSharedMemorySize, smem_dn);
    cudaFuncSetAttribute(down_kernel<false>, cudaFuncAttributeMaxDynamicSharedMemorySize, smem_dn);

    // 3) gate+up (fp16 tensor path)
    dim3 g1(MSH / GUBN, NTOK / BM, NJOBS);   // 16 x 16 x 9
    gateup_kernel<<<g1, 256, smem_gu>>>();

    // 4) down: shared writes y fully, routed accumulates on top
    dim3 g2s(H / DBN, NTOK / BM, 1);
    down_kernel<true><<<g2s, 256, smem_dn>>>(y);
    dim3 g2r(H / DBN, NTOK / BM, NEXP);
    down_kernel<false><<<g2r, 256, smem_dn>>>(y);
}

// round 13
// speedup vs baseline: 1.0428x; 1.0428x over previous
#include <cuda_runtime.h>
#include <cuda_fp16.h>
#include <cstdint>

// Problem constants
#define H     2048
#define NTOK  2048      // B*S
#define MR    512       // routed intermediate
#define MSH   1024      // shared intermediate
#define NEXP  8
#define NJOBS 9

// GEMM tiling (fp16 operands, m16n8k16)
#define BM   128
#define GUBN 64         // gateup N tile (per matrix g/u)
#define DBN  128        // down N tile
#define BKH  64         // K halfs per smem tile (4 x k16 steps)
#define S36  36         // smem row stride in uint32 words (32 half2 + 4 pad)
#define NSTG 3

// -------- scratch (no mallocs allowed) --------
__device__ int   d_counts[NEXP];
__device__ int   d_tok[NEXP * NTOK];
__device__ float d_wt [NEXP * NTOK];

__device__ __half g_xh  [(size_t)NTOK * H];
__device__ __half g_wgT [(size_t)NEXP * MR * H];   // [e][n=MR][k=H]
__device__ __half g_wuT [(size_t)NEXP * MR * H];
__device__ __half g_swgT[(size_t)MSH * H];         // [n=MSH][k=H]
__device__ __half g_swuT[(size_t)MSH * H];
__device__ __half g_wdT [(size_t)NEXP * H * MR];   // [e][n=H][k=MR]
__device__ __half g_swdT[(size_t)H * MSH];         // [n=H][k=MSH]
#define HB_SHOFF ((size_t)NEXP * NTOK * MR)
__device__ __half g_hb[HB_SHOFF + (size_t)NTOK * MSH];

// -------- helpers --------
__device__ __forceinline__ void cp16(void* smem_dst, const void* gmem_src) {
    uint32_t s = (uint32_t)__cvta_generic_to_shared(smem_dst);
    asm volatile("cp.async.cg.shared.global [%0], [%1], 16;\n" :: "r"(s), "l"(gmem_src));
}
__device__ __forceinline__ void cp_commit() { asm volatile("cp.async.commit_group;\n"); }
__device__ __forceinline__ void cp_wait0()  { asm volatile("cp.async.wait_group 0;\n"); }
__device__ __forceinline__ void cp_wait1()  { asm volatile("cp.async.wait_group 1;\n"); }

// m16n8k16 fp16 MMA, fp32 accumulate
__device__ __forceinline__ void mma_f16(float* c, const uint32_t* a, const uint32_t* b) {
    asm volatile(
        "mma.sync.aligned.m16n8k16.row.col.f32.f16.f16.f32 "
        "{%0,%1,%2,%3}, {%4,%5,%6,%7}, {%8,%9}, {%0,%1,%2,%3};\n"
        : "+f"(c[0]), "+f"(c[1]), "+f"(c[2]), "+f"(c[3])
        : "r"(a[0]), "r"(a[1]), "r"(a[2]), "r"(a[3]),
          "r"(b[0]), "r"(b[1]));
}

// -------- kernel A1: transpose+convert all weights to fp16 [N][K] --------
// 32(k) x 64(n) tiles, float4 reads AND float4 (8-half) writes. 15360 blocks.
__global__ void transpose_cvt_kernel(
    const float* __restrict__ Wg,  const float* __restrict__ Wu,
    const float* __restrict__ sWg, const float* __restrict__ sWu,
    const float* __restrict__ Wd,  const float* __restrict__ sWd)
{
    __shared__ alignas(16) __half st[64][40];
    int b = blockIdx.x;
    const float* src; __half* dst; int K, N;
    // tiles/segment: Wg 4096, Wu 4096, sWg 1024, sWu 1024, Wd 4096, sWd 1024
    if (b < 4096)       { int e = b >> 9; b &= 511; src = Wg  + (size_t)e * H * MR; dst = g_wgT + (size_t)e * MR * H; K = H;   N = MR; }
    else if (b < 8192)  { b -= 4096; int e = b >> 9; b &= 511; src = Wu + (size_t)e * H * MR; dst = g_wuT + (size_t)e * MR * H; K = H; N = MR; }
    else if (b < 9216)  { b -= 8192;  src = sWg; dst = g_swgT; K = H;   N = MSH; }
    else if (b < 10240) { b -= 9216;  src = sWu; dst = g_swuT; K = H;   N = MSH; }
    else if (b < 14336) { b -= 10240; int e = b >> 9; b &= 511; src = Wd + (size_t)e * MR * H; dst = g_wdT + (size_t)e * H * MR; K = MR; N = H; }
    else                { b -= 14336; src = sWd; dst = g_swdT; K = MSH; N = H; }

    int tN = N / 64;
    int bk = b / tN, bn = b % tN;
    int t = threadIdx.x;

    // read: 32k x 64n floats = 512 float4 -> 2/thread; stage transposed
#pragma unroll
    for (int j = 0; j < 2; j++) {
        int idx = t + j * 256;
        int kl = idx >> 4;            // 0..31
        int nl = (idx & 15) * 4;      // 0..60
        float4 v = *(const float4*)(src + (size_t)(bk * 32 + kl) * N + bn * 64 + nl);
        st[nl + 0][kl] = __float2half_rn(v.x);
        st[nl + 1][kl] = __float2half_rn(v.y);
        st[nl + 2][kl] = __float2half_rn(v.z);
        st[nl + 3][kl] = __float2half_rn(v.w);
    }
    __syncthreads();
    // write: 64n rows x 32k halfs = 256 x 16B -> 1/thread
    int nr = t >> 2;              // 0..63
    int kc = (t & 3) * 8;         // 0..24
    *(uint4*)(dst + (size_t)(bn * 64 + nr) * K + bk * 32 + kc) = *(uint4*)&st[nr][kc];
}

// -------- kernel A2: x -> fp16 + reset counts --------
__global__ void cvt_x_kernel(const float4* __restrict__ x) {
    if (blockIdx.x == 0 && threadIdx.x < NEXP) d_counts[threadIdx.x] = 0;
    __half2* d = reinterpret_cast<__half2*>(g_xh);
    const size_t total = (size_t)NTOK * H / 4;
    size_t stride = (size_t)gridDim.x * blockDim.x;
    for (size_t i = (size_t)blockIdx.x * blockDim.x + threadIdx.x; i < total; i += stride) {
        float4 v = x[i];
        d[2 * i]     = __floats2half2_rn(v.x, v.y);
        d[2 * i + 1] = __floats2half2_rn(v.z, v.w);
    }
}

// -------- kernel 1: gate logits + top2 + softmax + route lists --------
// 2 warps per token (each covers H/2), smem pair-reduce, then 1 lane finalizes.
__global__ void gate_kernel(const float* __restrict__ x, const float* __restrict__ gw) {
    __shared__ float part[4][2][NEXP];   // [token-in-block][half][expert]
    int wib  = threadIdx.x >> 5;         // 0..7
    int lane = threadIdx.x & 31;
    int tl   = wib >> 1;                 // token-in-block 0..3
    int half = wib & 1;
    int t    = blockIdx.x * 4 + tl;

    const float4* x4 = reinterpret_cast<const float4*>(x + (size_t)t * H) + half * (H / 8);
    const float4* g4 = reinterpret_cast<const float4*>(gw) + half * (H / 8);
    float acc[NEXP];
#pragma unroll
    for (int e = 0; e < NEXP; e++) acc[e] = 0.f;
#pragma unroll
    for (int i = 0; i < H / 8 / 32; i++) {       // 8 iterations
        float4 xv = x4[i * 32 + lane];
#pragma unroll
        for (int e = 0; e < NEXP; e++) {
            float4 gv = __ldg(&g4[e * (H / 4) + i * 32 + lane]);
            acc[e] += xv.x * gv.x + xv.y * gv.y + xv.z * gv.z + xv.w * gv.w;
        }
    }
#pragma unroll
    for (int e = 0; e < NEXP; e++)
#pragma unroll
        for (int o = 16; o; o >>= 1) acc[e] += __shfl_xor_sync(0xffffffffu, acc[e], o);
    if (lane < NEXP) part[tl][half][lane] = acc[lane];
    __syncthreads();

    // one lane per token finalizes (warp 0, lanes 0..3 handle tokens 0..3)
    if (wib == 0 && lane < 4) {
        int tok = blockIdx.x * 4 + lane;
        float v[NEXP];
#pragma unroll
        for (int e = 0; e < NEXP; e++) v[e] = part[lane][0][e] + part[lane][1][e];
        int i0 = 0; float v0 = v[0];
#pragma unroll
        for (int e = 1; e < NEXP; e++) if (v[e] > v0) { v0 = v[e]; i0 = e; }
        int i1 = -1; float v1 = -1e30f;
#pragma unroll
        for (int e = 0; e < NEXP; e++) if (e != i0 && v[e] > v1) { v1 = v[e]; i1 = e; }
        float e1 = __expf(v1 - v0);
        float s  = 1.f + e1;
        float w0 = 1.f / s, w1 = e1 / s;
        int p0 = atomicAdd(&d_counts[i0], 1);
        d_tok[i0 * NTOK + p0] = tok; d_wt[i0 * NTOK + p0] = w0;
        int p1 = atomicAdd(&d_counts[i1], 1);
        d_tok[i1 * NTOK + p1] = tok; d_wt[i1 * NTOK + p1] = w1;
    }
}

// -------- kernel 2: fp16 gate+up dual-GEMM + SiLU*u epilogue --------
__global__ __launch_bounds__(256, 2) void gateup_kernel() {
    const int  job = blockIdx.z;
    const bool sh  = (job == NEXP);
    const int  Mdim = sh ? MSH : MR;
    const int  cnt  = sh ? NTOK : d_counts[job];
    const int  row0 = blockIdx.y * BM;
    const int  col0 = blockIdx.x * GUBN;
    if (row0 >= cnt || col0 >= Mdim) return;

    const __half* BgT = sh ? g_swgT : g_wgT + (size_t)job * MR * H;
    const __half* BuT = sh ? g_swuT : g_wuT + (size_t)job * MR * H;

    extern __shared__ uint32_t smp[];
    uint32_t* As  = smp;                        // [NSTG][BM*S36]
    uint32_t* Bgs = smp + NSTG * BM * S36;      // [NSTG][GUBN*S36]
    uint32_t* Bus = Bgs + NSTG * GUBN * S36;

    const int tid = threadIdx.x;
    const int lane = tid & 31;
    const int wid = tid >> 5;
    const int warp_m = wid & 3;
    const int warp_n = wid >> 2;
    const int g_r = lane >> 2;
    const int g_c = lane & 3;

    uint32_t aoff[4]; int adst[4];
#pragma unroll
    for (int j = 0; j < 4; j++) {
        int idx = tid + j * 256;
        int m = idx >> 3, kc = idx & 7;
        int gl = row0 + m; if (gl >= cnt) gl = cnt - 1;
        int tok = sh ? gl : d_tok[job * NTOK + gl];
        aoff[j] = (uint32_t)(tok * H + kc * 8);
        adst[j] = m * S36 + kc * 4;
    }
    uint32_t boff[2]; int bdst[2];
#pragma unroll
    for (int j = 0; j < 2; j++) {
        int idx = tid + j * 256;
        int n = idx >> 3, kc = idx & 7;
        boff[j] = (uint32_t)((col0 + n) * H + kc * 8);
        bdst[j] = n * S36 + kc * 4;
    }

    float accg[2][4][4], accu[2][4][4];
#pragma unroll
    for (int a = 0; a < 2; a++)
#pragma unroll
        for (int b = 0; b < 4; b++)
#pragma unroll
            for (int c = 0; c < 4; c++) { accg[a][b][c] = 0.f; accu[a][b][c] = 0.f; }

    const int KT = H / BKH;   // 32

#pragma unroll
    for (int s = 0; s < 2; s++) {
        uint32_t adv = (uint32_t)s * BKH;
#pragma unroll
        for (int j = 0; j < 4; j++) cp16(As + s * BM * S36 + adst[j], g_xh + aoff[j] + adv);
#pragma unroll
        for (int j = 0; j < 2; j++) {
            cp16(Bgs + s * GUBN * S36 + bdst[j], BgT + boff[j] + adv);
            cp16(Bus + s * GUBN * S36 + bdst[j], BuT + boff[j] + adv);
        }
        cp_commit();
    }

    for (int kt = 0; kt < KT; kt++) {
        if (kt < KT - 1) cp_wait1(); else cp_wait0();
        __syncthreads();

        if (kt + 2 < KT) {
            int nb = (kt + 2) % NSTG;
            uint32_t adv = (uint32_t)(kt + 2) * BKH;
#pragma unroll
            for (int j = 0; j < 4; j++) cp16(As + nb * BM * S36 + adst[j], g_xh + aoff[j] + adv);
#pragma unroll
            for (int j = 0; j < 2; j++) {
                cp16(Bgs + nb * GUBN * S36 + bdst[j], BgT + boff[j] + adv);
                cp16(Bus + nb * GUBN * S36 + bdst[j], BuT + boff[j] + adv);
            }
            cp_commit();
        }

        const int st = kt % NSTG;
        const uint32_t* Ac  = As  + st * BM * S36;
        const uint32_t* Bgc = Bgs + st * GUBN * S36;
        const uint32_t* Buc = Bus + st * GUBN * S36;

#pragma unroll
        for (int ks = 0; ks < BKH / 16; ks++) {
            uint32_t af[2][4], bg[4][2], bu[4][2];
#pragma unroll
            for (int mf = 0; mf < 2; mf++) {
                int rb = warp_m * 32 + mf * 16 + g_r;
                af[mf][0] = Ac[rb * S36       + ks * 8 + g_c];
                af[mf][1] = Ac[(rb + 8) * S36 + ks * 8 + g_c];
                af[mf][2] = Ac[rb * S36       + ks * 8 + g_c + 4];
                af[mf][3] = Ac[(rb + 8) * S36 + ks * 8 + g_c + 4];
            }
#pragma unroll
            for (int nf = 0; nf < 4; nf++) {
                int cb = warp_n * 32 + nf * 8 + g_r;
                bg[nf][0] = Bgc[cb * S36 + ks * 8 + g_c];
                bg[nf][1] = Bgc[cb * S36 + ks * 8 + g_c + 4];
                bu[nf][0] = Buc[cb * S36 + ks * 8 + g_c];
                bu[nf][1] = Buc[cb * S36 + ks * 8 + g_c + 4];
            }
#pragma unroll
            for (int mf = 0; mf < 2; mf++)
#pragma unroll
                for (int nf = 0; nf < 4; nf++) {
                    mma_f16(accg[mf][nf], af[mf], bg[nf]);
                    mma_f16(accu[mf][nf], af[mf], bu[nf]);
                }
        }
    }

    __half* hb = g_hb + (sh ? HB_SHOFF : (size_t)job * NTOK * MR);
#pragma unroll
    for (int mf = 0; mf < 2; mf++)
#pragma unroll
        for (int nf = 0; nf < 4; nf++) {
            int c0 = col0 + warp_n * 32 + nf * 8 + g_c * 2;
#pragma unroll
            for (int half_r = 0; half_r < 2; half_r++) {
                int r = warp_m * 32 + mf * 16 + g_r + half_r * 8;
                int gr = row0 + r;
                if (gr < cnt) {
                    float g0 = accg[mf][nf][half_r * 2 + 0], u0 = accu[mf][nf][half_r * 2 + 0];
                    float g1 = accg[mf][nf][half_r * 2 + 1], u1 = accu[mf][nf][half_r * 2 + 1];
                    float h0 = g0 / (1.f + __expf(-g0)) * u0;
                    float h1 = g1 / (1.f + __expf(-g1)) * u1;
                    *reinterpret_cast<__half2*>(hb + (size_t)gr * Mdim + c0) =
                        __floats2half2_rn(h0, h1);
                }
            }
        }
}

// -------- kernel 3: fp16 down-proj --------
template <bool SHARED>
__global__ __launch_bounds__(256, 2) void down_kernel(float* __restrict__ y) {
    const int  job  = SHARED ? 0 : blockIdx.z;
    const int  Kdim = SHARED ? MSH : MR;
    const int  cnt  = SHARED ? NTOK : d_counts[job];
    const int  row0 = blockIdx.y * BM;
    const int  col0 = blockIdx.x * DBN;
    if (row0 >= cnt) return;

    const __half* Bp = SHARED ? g_swdT : g_wdT + (size_t)job * H * MR;
    const __half* Ap = SHARED ? g_hb + HB_SHOFF : g_hb + (size_t)job * NTOK * MR;

    extern __shared__ uint32_t smp[];
    uint32_t* As = smp;
    uint32_t* Bs = smp + NSTG * BM * S36;

    const int tid = threadIdx.x;
    const int lane = tid & 31;
    const int wid = tid >> 5;
    const int warp_m = wid & 3;
    const int warp_n = wid >> 2;
    const int g_r = lane >> 2;
    const int g_c = lane & 3;

    uint32_t aoff[4]; int adst[4];
#pragma unroll
    for (int j = 0; j < 4; j++) {
        int idx = tid + j * 256;
        int m = idx >> 3, kc = idx & 7;
        aoff[j] = (uint32_t)((row0 + m) * Kdim + kc * 8);
        adst[j] = m * S36 + kc * 4;
    }
    uint32_t boff[4]; int bdst[4];
#pragma unroll
    for (int j = 0; j < 4; j++) {
        int idx = tid + j * 256;
        int n = idx >> 3, kc = idx & 7;
        boff[j] = (uint32_t)((col0 + n) * Kdim + kc * 8);
        bdst[j] = n * S36 + kc * 4;
    }

    float acc[2][8][4];
#pragma unroll
    for (int a = 0; a < 2; a++)
#pragma unroll
        for (int b = 0; b < 8; b++)
#pragma unroll
            for (int c = 0; c < 4; c++) acc[a][b][c] = 0.f;

    const int KT = Kdim / BKH;

#pragma unroll
    for (int s = 0; s < 2; s++) {
        uint32_t adv = (uint32_t)s * BKH;
#pragma unroll
        for (int j = 0; j < 4; j++) cp16(As + s * BM * S36 + adst[j], Ap + aoff[j] + adv);
#pragma unroll
        for (int j = 0; j < 4; j++) cp16(Bs + s * DBN * S36 + bdst[j], Bp + boff[j] + adv);
        cp_commit();
    }

    for (int kt = 0; kt < KT; kt++) {
        if (kt < KT - 1) cp_wait1(); else cp_wait0();
        __syncthreads();

        if (kt + 2 < KT) {
            int nb = (kt + 2) % NSTG;
            uint32_t adv = (uint32_t)(kt + 2) * BKH;
#pragma unroll
            for (int j = 0; j < 4; j++) cp16(As + nb * BM * S36 + adst[j], Ap + aoff[j] + adv);
#pragma unroll
            for (int j = 0; j < 4; j++) cp16(Bs + nb * DBN * S36 + bdst[j], Bp + boff[j] + adv);
            cp_commit();
        }

        const int st = kt % NSTG;
        const uint32_t* Ac = As + st * BM * S36;
        const uint32_t* Bc = Bs + st * DBN * S36;

#pragma unroll
        for (int ks = 0; ks < BKH / 16; ks++) {
            uint32_t af[2][4], bf[8][2];
#pragma unroll
            for (int mf = 0; mf < 2; mf++) {
                int rb = warp_m * 32 + mf * 16 + g_r;
                af[mf][0] = Ac[rb * S36       + ks * 8 + g_c];
                af[mf][1] = Ac[(rb + 8) * S36 + ks * 8 + g_c];
                af[mf][2] = Ac[rb * S36       + ks * 8 + g_c + 4];
                af[mf][3] = Ac[(rb + 8) * S36 + ks * 8 + g_c + 4];
            }
#pragma unroll
            for (int nf = 0; nf < 8; nf++) {
                int cb = warp_n * 64 + nf * 8 + g_r;
                bf[nf][0] = Bc[cb * S36 + ks * 8 + g_c];
                bf[nf][1] = Bc[cb * S36 + ks * 8 + g_c + 4];
            }
#pragma unroll
            for (int mf = 0; mf < 2; mf++)
#pragma unroll
                for (int nf = 0; nf < 8; nf++)
                    mma_f16(acc[mf][nf], af[mf], bf[nf]);
        }
    }

#pragma unroll
    for (int mf = 0; mf < 2; mf++)
#pragma unroll
        for (int nf = 0; nf < 8; nf++)
#pragma unroll
            for (int i = 0; i < 4; i++) {
                int r = warp_m * 32 + mf * 16 + g_r + ((i >= 2) ? 8 : 0);
                int c = warp_n * 64 + nf * 8 + g_c * 2 + (i & 1);
                int gr = row0 + r;
                if (gr < cnt) {
                    if (SHARED) {
                        y[(size_t)gr * H + col0 + c] = acc[mf][nf][i];
                    } else {
                        int   tok = d_tok[job * NTOK + gr];
                        float w   = d_wt[job * NTOK + gr];
                        atomicAdd(&y[(size_t)tok * H + col0 + c], w * acc[mf][nf][i]);
                    }
                }
            }
}

extern "C" void kernel_launch(void* const* d_in, const int* in_sizes, int n_in,
                              void* d_out, int out_size) {
    const float* x   = (const float*)d_in[0];
    const float* gw  = (const float*)d_in[1];
    const float* Wg  = (const float*)d_in[2];
    const float* Wu  = (const float*)d_in[3];
    const float* Wd  = (const float*)d_in[4];
    const float* sWg = (const float*)d_in[5];
    const float* sWu = (const float*)d_in[6];
    const float* sWd = (const float*)d_in[7];
    float* y = (float*)d_out;

    // 1) prep
    transpose_cvt_kernel<<<15360, 256>>>(Wg, Wu, sWg, sWu, Wd, sWd);
    cvt_x_kernel<<<4096, 256>>>((const float4*)x);   // also resets d_counts

    // 2) routing (2 warps/token)
    gate_kernel<<<NTOK / 4, 256>>>(x, gw);

    const int smem_gu = NSTG * (BM * S36 + 2 * GUBN * S36) * 4;   // 110592
    const int smem_dn = NSTG * (BM * S36 + DBN * S36) * 4;        // 110592
    cudaFuncSetAttribute(gateup_kernel,      cudaFuncAttributeMaxDynamicSharedMemorySize, smem_gu);
    cudaFuncSetAttribute(down_kernel<true>,  cudaFuncAttributeMaxDynamicSharedMemorySize, smem_dn);
    cudaFuncSetAttribute(down_kernel<false>, cudaFuncAttributeMaxDynamicSharedMemorySize, smem_dn);

    // 3) gate+up
    dim3 g1(MSH / GUBN, NTOK / BM, NJOBS);
    gateup_kernel<<<g1, 256, smem_gu>>>();

    // 4) down
    dim3 g2s(H / DBN, NTOK / BM, 1);
    down_kernel<true><<<g2s, 256, smem_dn>>>(y);
    dim3 g2r(H / DBN, NTOK / BM, NEXP);
    down_kernel<false><<<g2r, 256, smem_dn>>>(y);
}